// round 17
// baseline (speedup 1.0000x reference)
#include <cuda_runtime.h>
#include <cuda_fp16.h>
#include <math.h>

typedef unsigned int u32;

// Problem constants
#define B_   16
#define H_   56
#define W_   56
#define C_   512
#define WS_  7
#define NH_  16
#define HD_  32
#define HID_ 2048
#define N_   49
#define NW_  64
#define L_   (H_ * W_)          // 3136
#define ROWS_ (B_ * L_)         // 50176
#define QKVC_ 1536
#define SCALE_ 0.17677669529663687f
#define EPS_ 1e-5f

// Scratch (device globals: allocation-free)
__device__ __half g_h  [ROWS_ * C_];
__device__ __half g_qkv[ROWS_ * QKVC_];
__device__ __half g_ao [ROWS_ * C_];
__device__ float  g_x2 [ROWS_ * C_];
__device__ __half g_hid[ROWS_ * HID_];
__device__ __half g_wtqkv[QKVC_ * C_];   // [1536][512]  (s*Wq^T | Wk^T | Wv^T)
__device__ __half g_wtp  [C_ * C_];
__device__ __half g_wt1  [HID_ * C_];
__device__ __half g_wt2  [C_ * HID_];
__device__ float  g_bqkv [QKVC_];

// ---------------------------------------------------------------------------
// Helpers
// ---------------------------------------------------------------------------
__device__ __forceinline__ void cp_async16(u32 saddr, const void* gptr) {
    asm volatile("cp.async.cg.shared.global [%0], [%1], 16;" :: "r"(saddr), "l"(gptr));
}
#define CP_COMMIT() asm volatile("cp.async.commit_group;")
#define CP_WAIT(n)  asm volatile("cp.async.wait_group %0;" :: "n"(n))

#define MMA_F16(ac, ar, b0, b1)                                                 \
    asm volatile(                                                               \
        "mma.sync.aligned.m16n8k16.row.col.f32.f16.f16.f32 "                    \
        "{%0,%1,%2,%3},{%4,%5,%6,%7},{%8,%9},{%0,%1,%2,%3};"                    \
        : "+f"(ac[0]), "+f"(ac[1]), "+f"(ac[2]), "+f"(ac[3])                    \
        : "r"(ar[0]), "r"(ar[1]), "r"(ar[2]), "r"(ar[3]), "r"(b0), "r"(b1))

#define LDSM_X4(r, a)                                                           \
    asm volatile("ldmatrix.sync.aligned.m8n8.x4.shared.b16 {%0,%1,%2,%3}, [%4];"\
        : "=r"((r)[0]), "=r"((r)[1]), "=r"((r)[2]), "=r"((r)[3]) : "r"(a))

#define LDSM_X4_T(r, a)                                                         \
    asm volatile("ldmatrix.sync.aligned.m8n8.x4.trans.shared.b16 {%0,%1,%2,%3}, [%4];"\
        : "=r"((r)[0]), "=r"((r)[1]), "=r"((r)[2]), "=r"((r)[3]) : "r"(a))

__device__ __forceinline__ u32 smem_u32(const void* p) {
    return (u32)__cvta_generic_to_shared(p);
}

// ---------------------------------------------------------------------------
// Unified weight prep: all transposes (32x32 tiles) + bias pack, one launch.
// Wq (and bq) are pre-scaled by SCALE_ (softmax scale folded into Q proj).
// ---------------------------------------------------------------------------
__global__ __launch_bounds__(256) void weight_prep_kernel(
    const float* __restrict__ Wq, const float* __restrict__ Wk,
    const float* __restrict__ Wv, const float* __restrict__ Wp,
    const float* __restrict__ W1, const float* __restrict__ W2,
    const float* __restrict__ bq, const float* __restrict__ bk,
    const float* __restrict__ bv,
    __half* __restrict__ dqkv, __half* __restrict__ dp,
    __half* __restrict__ d1, __half* __restrict__ d2,
    float* __restrict__ bdst)
{
    int id = blockIdx.x;
    const float* src;
    __half* dst;
    int R, Cc, tx32, ty32;
    float sc = 1.0f;
    if (id < 768) {
        int z = id >> 8, r = id & 255;
        src = (z == 0) ? Wq : (z == 1) ? Wk : Wv;
        if (z == 0) sc = SCALE_;
        dst = dqkv + (size_t)z * 512 * C_;
        R = C_; Cc = C_; tx32 = r & 15; ty32 = r >> 4;
    } else if (id < 1024) {
        int r = id - 768;
        src = Wp; dst = dp; R = C_; Cc = C_; tx32 = r & 15; ty32 = r >> 4;
    } else if (id < 2048) {
        int r = id - 1024;
        src = W1; dst = d1; R = C_; Cc = HID_; tx32 = r & 63; ty32 = r >> 6;
    } else {
        int r = id - 2048;
        src = W2; dst = d2; R = HID_; Cc = C_; tx32 = r & 15; ty32 = r >> 4;
    }

    __shared__ float tile[32][33];
    int bx = tx32 * 32, by = ty32 * 32;
    int tx = threadIdx.x & 31, ty = threadIdx.x >> 5;   // 32 x 8
    #pragma unroll
    for (int i = 0; i < 32; i += 8)
        tile[ty + i][tx] = src[(size_t)(by + ty + i) * Cc + bx + tx];
    __syncthreads();
    #pragma unroll
    for (int i = 0; i < 32; i += 8)
        dst[(size_t)(bx + ty + i) * R + by + tx] =
            __float2half_rn(tile[tx][ty + i] * sc);

    if (id == 0) {
        for (int i = threadIdx.x; i < QKVC_; i += 256)
            bdst[i] = i < 512 ? bq[i] * SCALE_
                              : (i < 1024 ? bk[i - 512] : bv[i - 1024]);
    }
}

// ---------------------------------------------------------------------------
// LayerNorm: warp-per-row (512 floats = 16/lane), 8 rows/block, no smem.
// fp32 in, fp16 out.
// ---------------------------------------------------------------------------
__global__ __launch_bounds__(256) void ln_kernel(const float* __restrict__ x,
                                                 const float* __restrict__ g,
                                                 const float* __restrict__ b,
                                                 __half* __restrict__ out) {
    int warp = threadIdx.x >> 5, lane = threadIdx.x & 31;
    int row = blockIdx.x * 8 + warp;
    const float4* xr = (const float4*)(x + (size_t)row * C_);
    const float4* gr = (const float4*)g;
    const float4* br = (const float4*)b;

    float4 v[4];
    float s = 0.0f, s2 = 0.0f;
    #pragma unroll
    for (int i = 0; i < 4; i++) {
        v[i] = xr[i * 32 + lane];
        s  += v[i].x + v[i].y + v[i].z + v[i].w;
        s2 += v[i].x * v[i].x + v[i].y * v[i].y
            + v[i].z * v[i].z + v[i].w * v[i].w;
    }
    #pragma unroll
    for (int o = 16; o; o >>= 1) {
        s  += __shfl_xor_sync(0xffffffffu, s, o);
        s2 += __shfl_xor_sync(0xffffffffu, s2, o);
    }
    float mu   = s * (1.0f / C_);
    float var  = s2 * (1.0f / C_) - mu * mu;
    float rstd = rsqrtf(var + EPS_);

    __half2* op = (__half2*)(out + (size_t)row * C_);
    #pragma unroll
    for (int i = 0; i < 4; i++) {
        float4 gg = gr[i * 32 + lane];
        float4 bb = br[i * 32 + lane];
        __half2 h0 = __floats2half2_rn((v[i].x - mu) * rstd * gg.x + bb.x,
                                       (v[i].y - mu) * rstd * gg.y + bb.y);
        __half2 h1 = __floats2half2_rn((v[i].z - mu) * rstd * gg.z + bb.z,
                                       (v[i].w - mu) * rstd * gg.w + bb.w);
        op[(i * 32 + lane) * 2 + 0] = h0;
        op[(i * 32 + lane) * 2 + 1] = h1;
    }
}

// ---------------------------------------------------------------------------
// FP16 tensor-core GEMM: BK=32, 5-stage cp.async pipeline, ldmatrix frags.
// 102,400 B dynamic smem, occ 2 (204.8 KB < 228 KB carveout).
// ---------------------------------------------------------------------------
#define GBK 32
#define GSU 20                        // u32 stride per row
#define STG_U32 (128 * GSU)
#define GEMM_SMEM (10 * STG_U32 * 4)  // 102400 bytes (5 stages x A,B)

__global__ __launch_bounds__(256, 2) void mma_gemm(
    const __half* __restrict__ A, const __half* __restrict__ Bt,
    const float* __restrict__ bias, const float* __restrict__ res,
    float* __restrict__ Cf, __half* __restrict__ Ch,
    int M, int Nc, int K, int do_gelu)
{
    extern __shared__ __align__(16) u32 dynsm[];

    const int tid = threadIdx.x;
    const int bm = blockIdx.y * 128;
    const int bn = blockIdx.x * 128;
    const int warp = tid >> 5, lane = tid & 31;
    const int wr = warp >> 2, wc = warp & 3;
    const int grp = lane >> 2, tig = lane & 3;

    const int r0 = tid >> 1;
    const int c0 = (tid & 1) * 2;

    const __half* Ag = A  + (size_t)(bm + r0) * K + c0 * 8;
    const __half* Bg = Bt + (size_t)(bn + r0) * K + c0 * 8;
    const u32 stoff = (r0 * GSU + c0 * 4) * 4;

    const u32 base = smem_u32(dynsm);
    u32 bA[5], bB[5];
    #pragma unroll
    for (int i = 0; i < 5; i++) {
        bA[i] = base + i * STG_U32 * 4;
        bB[i] = base + (5 + i) * STG_U32 * 4;
    }

    const int rA = ((lane >> 3) & 1) * 8 + (lane & 7);
    const int cA = (lane >> 4) * 4;
    const int rB = (lane >> 4) * 8 + (lane & 7);
    const int cB = ((lane >> 3) & 1) * 4;
    u32 aoff[4], boff[2];
    #pragma unroll
    for (int mt = 0; mt < 4; mt++)
        aoff[mt] = ((wr * 64 + mt * 16 + rA) * GSU + cA) * 4;
    #pragma unroll
    for (int p = 0; p < 2; p++)
        boff[p] = ((wc * 32 + p * 16 + rB) * GSU + cB) * 4;

    float acc[4][4][4];
    #pragma unroll
    for (int mt = 0; mt < 4; mt++)
        #pragma unroll
        for (int nt = 0; nt < 4; nt++)
            #pragma unroll
            for (int r = 0; r < 4; r++) acc[mt][nt][r] = 0.0f;

    // prologue: stages 0..3
    #pragma unroll
    for (int sg = 0; sg < 4; sg++) {
        cp_async16(bA[sg] + stoff, Ag + sg * GBK);
        cp_async16(bA[sg] + stoff + 16, Ag + sg * GBK + 8);
        cp_async16(bB[sg] + stoff, Bg + sg * GBK);
        cp_async16(bB[sg] + stoff + 16, Bg + sg * GBK + 8);
        CP_COMMIT();
    }

    const int NT = K / GBK;
    int cur = 0;
    for (int t = 0; t < NT; t++) {
        CP_WAIT(3);
        __syncthreads();

        if (t + 4 < NT) {
            int k0 = (t + 4) * GBK;
            int nx = cur + 4 >= 5 ? cur - 1 : cur + 4;
            cp_async16(bA[nx] + stoff, Ag + k0);
            cp_async16(bA[nx] + stoff + 16, Ag + k0 + 8);
            cp_async16(bB[nx] + stoff, Bg + k0);
            cp_async16(bB[nx] + stoff + 16, Bg + k0 + 8);
        }
        CP_COMMIT();

        const u32 cA0 = bA[cur], cB0 = bB[cur];
        #pragma unroll
        for (int kk = 0; kk < 2; kk++) {
            const u32 ko = kk * 32;
            u32 fragA[4][4];
            u32 fragB[2][4];
            #pragma unroll
            for (int mt = 0; mt < 4; mt++)
                LDSM_X4(fragA[mt], cA0 + aoff[mt] + ko);
            #pragma unroll
            for (int p = 0; p < 2; p++)
                LDSM_X4(fragB[p], cB0 + boff[p] + ko);
            #pragma unroll
            for (int mt = 0; mt < 4; mt++) {
                #pragma unroll
                for (int nt = 0; nt < 4; nt++)
                    MMA_F16(acc[mt][nt], fragA[mt],
                            fragB[nt >> 1][(nt & 1) * 2],
                            fragB[nt >> 1][(nt & 1) * 2 + 1]);
            }
        }

        cur = (cur + 1 == 5) ? 0 : cur + 1;
    }

    #pragma unroll
    for (int mt = 0; mt < 4; mt++) {
        #pragma unroll
        for (int i = 0; i < 2; i++) {
            int row = bm + wr * 64 + mt * 16 + grp + i * 8;
            #pragma unroll
            for (int nt = 0; nt < 4; nt++) {
                int col = bn + wc * 32 + nt * 8 + 2 * tig;
                float v0 = acc[mt][nt][2 * i + 0] + bias[col];
                float v1 = acc[mt][nt][2 * i + 1] + bias[col + 1];
                if (res) {
                    const float* rp = res + (size_t)row * Nc + col;
                    v0 += rp[0]; v1 += rp[1];
                }
                if (do_gelu) {
                    v0 = v0 * normcdff(v0);
                    v1 = v1 * normcdff(v1);
                }
                if (Ch) {
                    *(__half2*)(Ch + (size_t)row * Nc + col) = __floats2half2_rn(v0, v1);
                } else {
                    *(float2*)(Cf + (size_t)row * Nc + col) = make_float2(v0, v1);
                }
            }
        }
    }
}

// ---------------------------------------------------------------------------
// Tensor-core window attention, register softmax (no max pass: |S| bounded),
// cp.async gather, V row-major + ldmatrix.trans B fragments.
// One block per (window, head), 256 threads (8 warps: 4 m-tiles x 2 n-halves).
// ---------------------------------------------------------------------------
#define AQ_ST 20    // u32 row stride of Q/K/V smem (32 halfs + pad)
#define AV_ST 36    // u32 row stride of P smem (64 halfs + pad)

__global__ __launch_bounds__(256) void attn_kernel(
    const __half* __restrict__ qkv, const float* __restrict__ rel_bias,
    __half* __restrict__ ao)
{
    __shared__ __align__(16) u32 Qs[64 * AQ_ST];
    __shared__ __align__(16) u32 Ks[64 * AQ_ST];
    __shared__ __align__(16) u32 Vs[64 * AQ_ST];
    __shared__ __align__(16) u32 Ps[64 * AV_ST];
    __shared__ float rsum[2][64];

    int w = blockIdx.x;
    int head = blockIdx.y;
    int b  = w >> 6;
    int wi = w & 63;
    int wr = wi >> 3;
    int wc = wi & 7;
    int tid = threadIdx.x;
    int warp = tid >> 5, lane = tid & 31;
    int grp = lane >> 2, tig = lane & 3;
    int base_col = head * HD_;

    // gather Q/K/V rows via cp.async (rows 0..48 only)
    if (tid < N_ * 4) {
        int n = tid >> 2, f = (tid & 3) * 8;
        int ir = n / 7, ic = n - (n / 7) * 7;
        size_t row = (size_t)(b * 56 + wr * 7 + ir) * 56 + (wc * 7 + ic);
        size_t off = row * QKVC_ + base_col + f;
        u32 so = (n * AQ_ST + f / 2) * 4;
        cp_async16(smem_u32(Qs) + so, qkv + off);
        cp_async16(smem_u32(Ks) + so, qkv + off + 512);
        cp_async16(smem_u32(Vs) + so, qkv + off + 1024);
    }
    // zero V pad rows 49..63 (only pads that can poison O via NaN*0)
    for (int i = tid; i < 15 * AQ_ST; i += 256)
        Vs[N_ * AQ_ST + i] = 0;
    CP_COMMIT();
    CP_WAIT(0);
    __syncthreads();

    // ldmatrix lane addressing
    const int rA = ((lane >> 3) & 1) * 8 + (lane & 7);
    const int cA = (lane >> 4) * 4;
    const int rB = (lane >> 4) * 8 + (lane & 7);
    const int cB = ((lane >> 3) & 1) * 4;

    const int mi = warp & 3;        // m-tile
    const int nh = warp >> 2;       // n-half
    const int row0 = mi * 16 + grp;
    const int row1 = row0 + 8;

    // ---- S = Q.K^T (registers) ----
    float accS[4][4];
    #pragma unroll
    for (int nt = 0; nt < 4; nt++)
        #pragma unroll
        for (int r = 0; r < 4; r++) accS[nt][r] = 0.0f;
    {
        u32 aoffQ = smem_u32(Qs) + ((mi * 16 + rA) * AQ_ST + cA) * 4;
        #pragma unroll
        for (int kk = 0; kk < 2; kk++) {
            u32 ko = kk * 32;
            u32 fa[4];
            LDSM_X4(fa, aoffQ + ko);
            #pragma unroll
            for (int p = 0; p < 2; p++) {
                u32 fb[4];
                LDSM_X4(fb, smem_u32(Ks) +
                            ((nh * 32 + p * 16 + rB) * AQ_ST + cB) * 4 + ko);
                MMA_F16(accS[p * 2 + 0], fa, fb[0], fb[1]);
                MMA_F16(accS[p * 2 + 1], fa, fb[2], fb[3]);
            }
        }
    }

    // ---- exp(S + rel_bias) in-register; invalid lanes -> 0 ----
    float vals[2][8];
    float s0 = 0.0f, s1 = 0.0f;
    {
        const float* rb = rel_bias + head * (N_ * N_);
        #pragma unroll
        for (int nt = 0; nt < 4; nt++) {
            int j0 = nh * 32 + nt * 8 + 2 * tig;
            #pragma unroll
            for (int c = 0; c < 2; c++) {
                int j = j0 + c;
                float e0 = (j < N_ && row0 < N_)
                    ? __expf(accS[nt][c]     + rb[row0 * N_ + j]) : 0.0f;
                float e1 = (j < N_ && row1 < N_)
                    ? __expf(accS[nt][2 + c] + rb[row1 * N_ + j]) : 0.0f;
                vals[0][nt * 2 + c] = e0;
                vals[1][nt * 2 + c] = e1;
                s0 += e0;
                s1 += e1;
            }
        }
    }

    // ---- row sum ----
    #pragma unroll
    for (int o = 1; o <= 2; o <<= 1) {
        s0 += __shfl_xor_sync(0xffffffffu, s0, o);
        s1 += __shfl_xor_sync(0xffffffffu, s1, o);
    }
    if (tig == 0) { rsum[nh][row0] = s0; rsum[nh][row1] = s1; }
    __syncthreads();
    float inv0 = 1.0f / (rsum[0][row0] + rsum[1][row0]);
    float inv1 = 1.0f / (rsum[0][row1] + rsum[1][row1]);

    // ---- write P fp16 (full 64x64; pads = 0) ----
    {
        __half2* ph2 = (__half2*)Ps;
        #pragma unroll
        for (int nt = 0; nt < 4; nt++) {
            int jh = (nh * 32 + nt * 8 + 2 * tig) >> 1;
            ph2[row0 * AV_ST + jh] =
                __floats2half2_rn(vals[0][nt * 2] * inv0, vals[0][nt * 2 + 1] * inv0);
            ph2[row1 * AV_ST + jh] =
                __floats2half2_rn(vals[1][nt * 2] * inv1, vals[1][nt * 2 + 1] * inv1);
        }
    }
    __syncthreads();

    // ---- O = P @ V^T (V row-major, trans ldmatrix for B) ----
    {
        float accO[2][4];
        #pragma unroll
        for (int nt = 0; nt < 2; nt++)
            #pragma unroll
            for (int r = 0; r < 4; r++) accO[nt][r] = 0.0f;

        u32 aoffP = smem_u32(Ps) + ((mi * 16 + rA) * AV_ST + cA) * 4;
        int matv = lane >> 3, rV = lane & 7;
        u32 boffV = smem_u32(Vs) +
                    (((matv & 1) * 8 + rV) * AQ_ST) * 4 +
                    nh * 32 + (matv >> 1) * 16;
        #pragma unroll
        for (int kk = 0; kk < 4; kk++) {
            u32 fa[4], fbt[4];
            LDSM_X4(fa, aoffP + kk * 32);
            LDSM_X4_T(fbt, boffV + kk * 16 * AQ_ST * 4);
            MMA_F16(accO[0], fa, fbt[0], fbt[1]);
            MMA_F16(accO[1], fa, fbt[2], fbt[3]);
        }

        #pragma unroll
        for (int ih = 0; ih < 2; ih++) {
            int i = mi * 16 + grp + ih * 8;
            if (i < N_) {
                int ir = i / 7, ic = i - (i / 7) * 7;
                size_t row = (size_t)(b * 56 + wr * 7 + ir) * 56 + (wc * 7 + ic);
                #pragma unroll
                for (int nt = 0; nt < 2; nt++) {
                    int d = nh * 16 + nt * 8 + 2 * tig;
                    *(__half2*)(ao + row * C_ + base_col + d) =
                        __floats2half2_rn(accO[nt][2 * ih], accO[nt][2 * ih + 1]);
                }
            }
        }
    }
}

// ---------------------------------------------------------------------------
// Launch
// ---------------------------------------------------------------------------
extern "C" void kernel_launch(void* const* d_in, const int* in_sizes, int n_in,
                              void* d_out, int out_size)
{
    const float* x    = (const float*)d_in[0];
    const float* Wq   = (const float*)d_in[1];
    const float* bq   = (const float*)d_in[2];
    const float* Wk   = (const float*)d_in[3];
    const float* bk   = (const float*)d_in[4];
    const float* Wv   = (const float*)d_in[5];
    const float* bv   = (const float*)d_in[6];
    const float* Wp   = (const float*)d_in[7];
    const float* bp   = (const float*)d_in[8];
    const float* rel  = (const float*)d_in[9];
    const float* g1   = (const float*)d_in[10];
    const float* b1   = (const float*)d_in[11];
    const float* g2   = (const float*)d_in[12];
    const float* b2   = (const float*)d_in[13];
    const float* W1   = (const float*)d_in[14];
    const float* bfc1 = (const float*)d_in[15];
    const float* W2   = (const float*)d_in[16];
    const float* bfc2 = (const float*)d_in[17];
    float* out = (float*)d_out;

    __half *h, *qkv, *ao, *hid, *wtqkv, *wtp, *wt1, *wt2;
    float *x2, *bqkv;
    cudaGetSymbolAddress((void**)&h,     g_h);
    cudaGetSymbolAddress((void**)&qkv,   g_qkv);
    cudaGetSymbolAddress((void**)&ao,    g_ao);
    cudaGetSymbolAddress((void**)&x2,    g_x2);
    cudaGetSymbolAddress((void**)&hid,   g_hid);
    cudaGetSymbolAddress((void**)&wtqkv, g_wtqkv);
    cudaGetSymbolAddress((void**)&wtp,   g_wtp);
    cudaGetSymbolAddress((void**)&wt1,   g_wt1);
    cudaGetSymbolAddress((void**)&wt2,   g_wt2);
    cudaGetSymbolAddress((void**)&bqkv,  g_bqkv);

    cudaFuncSetAttribute(mma_gemm, cudaFuncAttributeMaxDynamicSharedMemorySize,
                         GEMM_SMEM);

    // Unified weight prep (all transposes + bias pack; Wq/bq pre-scaled)
    weight_prep_kernel<<<3072, 256>>>(Wq, Wk, Wv, Wp, W1, W2, bq, bk, bv,
                                      wtqkv, wtp, wt1, wt2, bqkv);

    // LN1 -> h (fp16)   (warp-per-row, 8 rows/block)
    ln_kernel<<<ROWS_ / 8, 256>>>(x, g1, b1, h);

    // Fused QKV projection (N = 1536) -> qkv (fp16)
    mma_gemm<<<dim3(QKVC_ / 128, ROWS_ / 128), 256, GEMM_SMEM>>>(
        h, wtqkv, bqkv, nullptr, nullptr, qkv, ROWS_, QKVC_, C_, 0);

    // Windowed attention (tensor-core, register softmax) -> ao (fp16)
    attn_kernel<<<dim3(B_ * NW_, NH_), 256>>>(qkv, rel, ao);

    // Output projection + residual: x2 = x + ao @ Wp + bp (fp32)
    mma_gemm<<<dim3(C_ / 128, ROWS_ / 128), 256, GEMM_SMEM>>>(
        ao, wtp, bp, x, x2, nullptr, ROWS_, C_, C_, 0);

    // LN2 -> h (fp16)
    ln_kernel<<<ROWS_ / 8, 256>>>(x2, g2, b2, h);

    // MLP fc1 + exact GELU -> hid (fp16)
    mma_gemm<<<dim3(HID_ / 128, ROWS_ / 128), 256, GEMM_SMEM>>>(
        h, wt1, bfc1, nullptr, nullptr, hid, ROWS_, HID_, C_, 1);

    // MLP fc2 + residual -> out (fp32)
    mma_gemm<<<dim3(C_ / 128, ROWS_ / 128), 256, GEMM_SMEM>>>(
        hid, wt2, bfc2, x2, out, nullptr, ROWS_, C_, HID_, 0);
}